// round 8
// baseline (speedup 1.0000x reference)
#include <cuda_runtime.h>
#include <cuda_fp16.h>
#include <math.h>
#include <float.h>
#include <stdint.h>

// Shapes (fixed): z_e [32,64,64,64] f32, emb [512,64] f32.
#define N_TOK    131072
#define HW       4096
#define OFF_SCAL 8388608
#define OFF_IDX  8388613

// Scratch (static device globals: allocation-free).
// g_bhalf: per code 64 fp16 (one 128B row), pre-swizzled in 16B units (u ^= code&7).
__device__ __align__(16) uint32_t g_bhalf[512 * 32];
__device__ float        g_bnorm[512];
__device__ float        g_bmax2;     // max ||e_k||^2 (monotone across replays: idempotent)
__device__ int          g_idx[N_TOK];
__device__ unsigned int g_counts[512];
__device__ double       g_dsum;
__device__ int          g_nflag;
__device__ int          g_flag[N_TOK];

// ---------------- helpers ----------------
__device__ __forceinline__ uint32_t smem_u32(const void* p) {
    uint32_t a;
    asm("{ .reg .u64 t; cvta.to.shared.u64 t, %1; cvt.u32.u64 %0, t; }"
        : "=r"(a) : "l"(p));
    return a;
}
__device__ __forceinline__ uint32_t packh(float lo, float hi) {
    uint32_t r;
    asm("cvt.rn.f16x2.f32 %0, %1, %2;" : "=r"(r) : "f"(hi), "f"(lo));
    return r;
}
__device__ __forceinline__ void ldsm4(uint32_t b[4], uint32_t addr) {
    asm volatile("ldmatrix.sync.aligned.m8n8.x4.shared.b16 {%0,%1,%2,%3}, [%4];"
                 : "=r"(b[0]), "=r"(b[1]), "=r"(b[2]), "=r"(b[3]) : "r"(addr));
}
__device__ __forceinline__ void mma16816(float c[4], const uint32_t a[4],
                                         uint32_t b0, uint32_t b1) {
    asm volatile("mma.sync.aligned.m16n8k16.row.col.f32.f16.f16.f32 "
                 "{%0,%1,%2,%3}, {%4,%5,%6,%7}, {%8,%9}, {%0,%1,%2,%3};"
                 : "+f"(c[0]), "+f"(c[1]), "+f"(c[2]), "+f"(c[3])
                 : "r"(a[0]), "r"(a[1]), "r"(a[2]), "r"(a[3]), "r"(b0), "r"(b1));
}

// ---- prep: code norms, max norm, pre-swizzled fp16 codebook, zero accumulators ----
__global__ void vq_prep(const float* __restrict__ emb) {
    int k = blockIdx.x * 256 + threadIdx.x;   // 0..511
    const float* e = emb + k * 64;
    float s = 0.f;
    for (int d = 0; d < 64; ++d) s = fmaf(e[d], e[d], s);
    g_bnorm[k]  = s;
    g_counts[k] = 0u;
    atomicMax((int*)&g_bmax2, __float_as_int(s));   // positive floats: int-max == fp-max
    if (k == 0) { g_dsum = 0.0; g_nflag = 0; }

    uint32_t* row = g_bhalf + k * 32;
    int sw = k & 7;
    for (int u = 0; u < 8; ++u) {
        int d0 = 8 * u;
        uint32_t* dst = row + (u ^ sw) * 4;
        for (int w = 0; w < 4; ++w)
            dst[w] = packh(e[d0 + 2 * w], e[d0 + 2 * w + 1]);
    }
}

// ---------------- screening kernel (fp16 HMMA, K=64) ----------------
// smem: phase1 A-stage f32 [64][516] at 0 (132096 B); phase2 B fp16 at 0 (65536 B).
// bn / hist live above the A-stage.
#define SM_A     0
#define SM_B     0
#define SM_BN    132096
#define SM_HIST  134144
#define SM_TOTAL 136192

__global__ __launch_bounds__(512, 1)
void vq_screen(const float* __restrict__ z_e, float* __restrict__ out) {
    extern __shared__ __align__(16) unsigned char smem[];
    const uint32_t sb = smem_u32(smem);
    const int tid  = threadIdx.x;
    const int wid  = tid >> 5, lane = tid & 31;
    const int q    = lane >> 2;          // groupID (row within 8)
    const int c2   = (lane & 3) * 2;     // k/col base within tile
    const int strip = wid * 32;          // 32 tokens per warp

    const int nbase = blockIdx.x * 512;
    const float* zb = z_e + ((size_t)(nbase >> 12) << 18) + (nbase & (HW - 1));

    // --- phase 1: coalesced z copy into padded f32 stage [d][tok], pitch 516 ---
    float* sA = (float*)smem;
#pragma unroll
    for (int t = 0; t < 16; ++t) {
        int lin = t * 512 + tid;          // 8192 float4s
        int d   = lin >> 7;
        int t4  = lin & 127;
        float4 v = *(const float4*)(zb + (size_t)d * HW + t4 * 4);
        *(float4*)(sA + d * 516 + t4 * 4) = v;
    }
    for (int i = tid; i < 512; i += 512) {
        ((float*)(smem + SM_BN))[i]      = g_bnorm[i];
        ((uint32_t*)(smem + SM_HIST))[i] = 0u;
    }
    __syncthreads();

    // --- build fp16 A fragments + token norms from the stage (conflict-free LDS) ---
    uint32_t ah[2][4][4];
    float    anr[4];
#pragma unroll
    for (int mt = 0; mt < 2; ++mt) {
#pragma unroll
        for (int i = 0; i < 2; ++i) {
            int row = strip + mt * 16 + i * 8 + q;
            float acc = 0.f;
#pragma unroll
            for (int s = 0; s < 4; ++s) {
                int d0 = 16 * s + c2;
                float v0 = sA[(d0    ) * 516 + row];
                float v1 = sA[(d0 + 1) * 516 + row];
                float v2 = sA[(d0 + 8) * 516 + row];
                float v3 = sA[(d0 + 9) * 516 + row];
                acc = fmaf(v0, v0, acc); acc = fmaf(v1, v1, acc);
                acc = fmaf(v2, v2, acc); acc = fmaf(v3, v3, acc);
                ah[mt][s][i]     = packh(v0, v1);
                ah[mt][s][i + 2] = packh(v2, v3);
            }
            acc += __shfl_xor_sync(0xffffffffu, acc, 1);
            acc += __shfl_xor_sync(0xffffffffu, acc, 2);
            anr[mt * 2 + i] = acc;
        }
    }
    __syncthreads();

    // --- phase 2: B fp16 tile (pre-swizzled) into smem ---
    {
        const uint4* src = (const uint4*)g_bhalf;
        uint4*       dst = (uint4*)(smem + SM_B);
        for (int i = tid; i < 4096; i += 512) dst[i] = src[i];
    }
    __syncthreads();

    // --- per-lane ldmatrix addressing ---
    const int sub = (lane >> 3) & 1;                    // k-half
    const int rc  = ((lane & 16) >> 1) + (lane & 7);    // code row within 16
    const int sw7 = lane & 7;
    uint32_t boff[4];
#pragma unroll
    for (int ks = 0; ks < 4; ++ks)
        boff[ks] = (uint32_t)(((2 * ks + sub) ^ sw7) << 4);

    const float* bn = (const float*)(smem + SM_BN);
    float d1[4] = {FLT_MAX, FLT_MAX, FLT_MAX, FLT_MAX};
    float d2[4] = {FLT_MAX, FLT_MAX, FLT_MAX, FLT_MAX};
    int   i1[4] = {0, 0, 0, 0};

#pragma unroll 1
    for (int j = 0; j < 32; ++j) {      // 32 pairs of n8-tiles = 512 codes
        uint32_t bj = sb + SM_B + (uint32_t)(j * 16 + rc) * 128u;
        float c[2][2][4];
#pragma unroll
        for (int mt = 0; mt < 2; ++mt)
#pragma unroll
            for (int nt = 0; nt < 2; ++nt)
#pragma unroll
                for (int r = 0; r < 4; ++r) c[mt][nt][r] = 0.f;

#pragma unroll
        for (int ks = 0; ks < 4; ++ks) {
            uint32_t bf[4];
            ldsm4(bf, bj + boff[ks]);
#pragma unroll
            for (int mt = 0; mt < 2; ++mt) {
                mma16816(c[mt][0], ah[mt][ks], bf[0], bf[1]);
                mma16816(c[mt][1], ah[mt][ks], bf[2], bf[3]);
            }
        }

        int cb = j * 16 + c2;
        float bn0 = bn[cb],     bn1 = bn[cb + 1];
        float bn8 = bn[cb + 8], bn9 = bn[cb + 9];
#pragma unroll
        for (int mt = 0; mt < 2; ++mt)
#pragma unroll
            for (int half = 0; half < 2; ++half) {
                int r = mt * 2 + half;
                float A = anr[r];
                float v0 = fmaf(c[mt][0][half * 2],     -2.f, A + bn0);
                float v1 = fmaf(c[mt][0][half * 2 + 1], -2.f, A + bn1);
                float v2 = fmaf(c[mt][1][half * 2],     -2.f, A + bn8);
                float v3 = fmaf(c[mt][1][half * 2 + 1], -2.f, A + bn9);
                if (v0 < d1[r]) { d2[r] = d1[r]; d1[r] = v0; i1[r] = cb;     } else if (v0 < d2[r]) d2[r] = v0;
                if (v1 < d1[r]) { d2[r] = d1[r]; d1[r] = v1; i1[r] = cb + 1; } else if (v1 < d2[r]) d2[r] = v1;
                if (v2 < d1[r]) { d2[r] = d1[r]; d1[r] = v2; i1[r] = cb + 8; } else if (v2 < d2[r]) d2[r] = v2;
                if (v3 < d1[r]) { d2[r] = d1[r]; d1[r] = v3; i1[r] = cb + 9; } else if (v3 < d2[r]) d2[r] = v3;
            }
    }

    // --- merge top-2 across quad lanes; flag near-ties; emit the rest ---
    const float bmaxn = sqrtf(g_bmax2);
    float dloc = 0.f;
#pragma unroll
    for (int r = 0; r < 4; ++r) {
#pragma unroll
        for (int o = 1; o <= 2; o <<= 1) {
            float od1 = __shfl_xor_sync(0xffffffffu, d1[r], o);
            int   oi1 = __shfl_xor_sync(0xffffffffu, i1[r], o);
            float od2 = __shfl_xor_sync(0xffffffffu, d2[r], o);
            if (od1 < d1[r] || (od1 == d1[r] && oi1 < i1[r])) {
                d2[r] = fminf(d1[r], od2);
                d1[r] = od1; i1[r] = oi1;
            } else {
                d2[r] = fminf(d2[r], od1);
            }
        }
        if ((lane & 3) == 0) {
            int rowid = strip + (r & 1) * 8 + (r >> 1) * 16 + q;
            int n = nbase + rowid;
            float A = anr[r];
            // rigorous fp16-screen bound: 8.01*eps*||z||*Bmax + slack
            float theta = 3.92e-3f * bmaxn * sqrtf(fmaxf(A, 0.f)) + 1e-5f;
            if (d2[r] - d1[r] < theta) {
                int pos = atomicAdd(&g_nflag, 1);
                g_flag[pos] = n;
            } else {
                g_idx[n]         = i1[r];
                out[OFF_IDX + n] = (float)i1[r];
                atomicAdd(((uint32_t*)(smem + SM_HIST)) + i1[r], 1u);
                dloc += d1[r];
            }
        }
    }
#pragma unroll
    for (int o = 16; o; o >>= 1) dloc += __shfl_xor_sync(0xffffffffu, dloc, o);
    if (lane == 0) atomicAdd(&g_dsum, (double)dloc);

    __syncthreads();
    for (int i = tid; i < 512; i += 512) {
        uint32_t h = ((uint32_t*)(smem + SM_HIST))[i];
        if (h) atomicAdd(&g_counts[i], h);
    }
}

// ---- exact fp32 rescan of flagged (near-tie) tokens ----
__global__ void vq_fix(const float* __restrict__ z_e, const float* __restrict__ emb,
                       float* __restrict__ out) {
    int gw   = (blockIdx.x * 256 + threadIdx.x) >> 5;
    int lane = threadIdx.x & 31;
    int nf   = g_nflag;
    for (int i = gw; i < nf; i += 1024) {
        int n = g_flag[i];
        const float* zp = z_e + ((size_t)(n >> 12) << 18) + (n & (HW - 1));
        float z[64];
        float A = 0.f;
#pragma unroll
        for (int d = 0; d < 64; ++d) {
            z[d] = zp[(size_t)d << 12];
            A = fmaf(z[d], z[d], A);
        }
        float dmin = FLT_MAX;
        int   imin = 0;
        for (int c = lane; c < 512; c += 32) {
            const float* e = emb + c * 64;
            float dot = 0.f;
#pragma unroll
            for (int d = 0; d < 64; ++d) dot = fmaf(z[d], e[d], dot);
            float dist = fmaf(dot, -2.f, A + g_bnorm[c]);
            if (dist < dmin) { dmin = dist; imin = c; }
        }
#pragma unroll
        for (int o = 16; o; o >>= 1) {
            float od = __shfl_xor_sync(0xffffffffu, dmin, o);
            int   oi = __shfl_xor_sync(0xffffffffu, imin, o);
            if (od < dmin || (od == dmin && oi < imin)) { dmin = od; imin = oi; }
        }
        if (lane == 0) {
            g_idx[n]         = imin;
            out[OFF_IDX + n] = (float)imin;
            atomicAdd(&g_counts[imin], 1u);
            atomicAdd(&g_dsum, (double)dmin);
        }
    }
}

// ---- z_q scatter: out[b,d,h,w] = emb[idx[b,h,w], d] ----
__global__ void vq_zq(const float* __restrict__ emb, float* __restrict__ out) {
    int t  = blockIdx.x * 256 + threadIdx.x;
    int hw = t & (HW - 1);
    int d4 = (t >> 12) & 15;
    int b  = t >> 16;
    int idx = g_idx[(b << 12) + hw];
    const float4 e = *(const float4*)(emb + idx * 64 + d4 * 4);
    int base = (b << 18) + (d4 << 14) + hw;
    out[base        ] = e.x;
    out[base +  4096] = e.y;
    out[base +  8192] = e.z;
    out[base + 12288] = e.w;
}

// ---- scalars ----
__global__ void vq_finalize(float* __restrict__ out) {
    __shared__ float s_e[16];
    __shared__ int   s_u[16];
    int k = threadIdx.x;
    unsigned int c = g_counts[k];
    float p = (float)c * (1.0f / 131072.0f);
    float e = (c > 0) ? -p * logf(p) : 0.0f;
    int   u = (c > 0) ? 1 : 0;
#pragma unroll
    for (int o = 16; o; o >>= 1) {
        e += __shfl_xor_sync(0xffffffffu, e, o);
        u += __shfl_xor_sync(0xffffffffu, u, o);
    }
    if ((k & 31) == 0) { s_e[k >> 5] = e; s_u[k >> 5] = u; }
    __syncthreads();
    if (k == 0) {
        float ent = 0.0f; int used = 0;
        for (int i = 0; i < 16; ++i) { ent += s_e[i]; used += s_u[i]; }
        float avg = (float)(g_dsum * (1.0 / 131072.0));
        out[OFF_SCAL + 0] = 1.25f * avg;
        out[OFF_SCAL + 1] = expf(ent);
        out[OFF_SCAL + 2] = (float)used;
        out[OFF_SCAL + 3] = (float)used / 512.0f;
        out[OFF_SCAL + 4] = avg;
    }
}

extern "C" void kernel_launch(void* const* d_in, const int* in_sizes, int n_in,
                              void* d_out, int out_size) {
    const float* z_e = (const float*)d_in[0];
    const float* emb = (const float*)d_in[1];
    float*       out = (float*)d_out;

    cudaFuncSetAttribute(vq_screen, cudaFuncAttributeMaxDynamicSharedMemorySize,
                         SM_TOTAL);

    vq_prep<<<2, 256>>>(emb);
    vq_screen<<<N_TOK / 512, 512, SM_TOTAL>>>(z_e, out);
    vq_fix<<<128, 256>>>(z_e, emb, out);
    vq_zq<<<(N_TOK * 16) / 256, 256>>>(emb, out);
    vq_finalize<<<1, 512>>>(out);
}

// round 10
// speedup vs baseline: 4.0881x; 4.0881x over previous
#include <cuda_runtime.h>
#include <cuda_bf16.h>
#include <math.h>
#include <float.h>
#include <stdint.h>

// Shapes (fixed): z_e [32,64,64,64] f32, emb [512,64] f32.
#define N_TOK    131072
#define HW       4096
#define OFF_SCAL 8388608
#define OFF_IDX  8388613
#define THETA    1e-5f

// Scratch (static device globals: allocation-free).
// g_bsplit[0]: eh (bf16 high part), g_bsplit[1]: em (bf16 residual).
// Per code one 128B row (64 bf16), 16B units XOR-swizzled by (code&7).
__device__ __align__(16) uint32_t g_bsplit[2][512 * 32];
__device__ float        g_bnorm[512];
__device__ int          g_idx[N_TOK];
__device__ unsigned int g_counts[512];
__device__ double       g_dsum;
__device__ int          g_nflag;
__device__ int          g_flag[N_TOK];

// ---------------- helpers ----------------
__device__ __forceinline__ uint32_t smem_u32(const void* p) {
    uint32_t a;
    asm("{ .reg .u64 t; cvta.to.shared.u64 t, %1; cvt.u32.u64 %0, t; }"
        : "=r"(a) : "l"(p));
    return a;
}
__device__ __forceinline__ uint32_t packbf(float lo, float hi) {
    uint32_t r;
    asm("cvt.rn.bf16x2.f32 %0, %1, %2;" : "=r"(r) : "f"(hi), "f"(lo));
    return r;
}
__device__ __forceinline__ void ldsm4(uint32_t b[4], uint32_t addr) {
    asm volatile("ldmatrix.sync.aligned.m8n8.x4.shared.b16 {%0,%1,%2,%3}, [%4];"
                 : "=r"(b[0]), "=r"(b[1]), "=r"(b[2]), "=r"(b[3]) : "r"(addr));
}
__device__ __forceinline__ void mma16816(float c[4], const uint32_t a[4],
                                         uint32_t b0, uint32_t b1) {
    asm volatile("mma.sync.aligned.m16n8k16.row.col.f32.bf16.bf16.f32 "
                 "{%0,%1,%2,%3}, {%4,%5,%6,%7}, {%8,%9}, {%0,%1,%2,%3};"
                 : "+f"(c[0]), "+f"(c[1]), "+f"(c[2]), "+f"(c[3])
                 : "r"(a[0]), "r"(a[1]), "r"(a[2]), "r"(a[3]), "r"(b0), "r"(b1));
}

// ---- prep: code norms, swizzled bf16 2-split codebook, zero accumulators ----
__global__ void vq_prep(const float* __restrict__ emb) {
    int k = blockIdx.x * 256 + threadIdx.x;   // 0..511
    const float* e = emb + k * 64;
    float s = 0.f;
    for (int d = 0; d < 64; ++d) s = fmaf(e[d], e[d], s);
    g_bnorm[k]  = s;
    g_counts[k] = 0u;
    if (k == 0) { g_dsum = 0.0; g_nflag = 0; }

    int sw = k & 7;
    for (int u = 0; u < 8; ++u) {                 // 8 x 16B units per row
        uint32_t* dh = g_bsplit[0] + k * 32 + (u ^ sw) * 4;
        uint32_t* dm = g_bsplit[1] + k * 32 + (u ^ sw) * 4;
        for (int w = 0; w < 4; ++w) {
            float v0 = e[8 * u + 2 * w], v1 = e[8 * u + 2 * w + 1];
            float h0 = __bfloat162float(__float2bfloat16(v0));
            float h1 = __bfloat162float(__float2bfloat16(v1));
            dh[w] = packbf(h0, h1);
            dm[w] = packbf(v0 - h0, v1 - h1);
        }
    }
}

// ---------------- screening kernel (bf16 2-split HMMA, 3 products) ----------------
// smem: phase1 A-stage f32 [64][260] at 0 (66560 B);
//       phase2 B: eh at 0 (65536), em at 65536 (65536); bn/hist above.
#define SM_EM    65536
#define SM_BN    131072
#define SM_HIST  133120
#define SM_TOTAL 135168

__global__ __launch_bounds__(512, 1)
void vq_screen(const float* __restrict__ z_e, float* __restrict__ out) {
    extern __shared__ __align__(16) unsigned char smem[];
    const uint32_t sb = smem_u32(smem);
    const int tid  = threadIdx.x;
    const int wid  = tid >> 5, lane = tid & 31;
    const int q    = lane >> 2;          // row within 8
    const int c2   = (lane & 3) * 2;     // col pair base
    const int strip = wid * 16;          // 16 tokens per warp

    const int nbase = blockIdx.x * 256;
    const float* zb = z_e + ((size_t)(nbase >> 12) << 18) + (nbase & (HW - 1));

    // --- phase 1: coalesced z copy into padded f32 stage [d][tok], pitch 260 ---
    float* sA = (float*)smem;
#pragma unroll
    for (int t = 0; t < 8; ++t) {
        int lin = t * 512 + tid;          // 4096 float4s
        int d   = lin >> 6;
        int t4  = lin & 63;
        float4 v = *(const float4*)(zb + (size_t)d * HW + t4 * 4);
        *(float4*)(sA + d * 260 + t4 * 4) = v;
    }
    ((float*)(smem + SM_BN))[tid]      = g_bnorm[tid];
    ((uint32_t*)(smem + SM_HIST))[tid] = 0u;
    __syncthreads();

    // --- build bf16 2-split A fragments + token norms (conflict-free LDS) ---
    // A fragment layout (m16n8k16 row-major): a0=(row q, k lo), a1=(row q+8, k lo),
    //                                         a2=(row q, k hi), a3=(row q+8, k hi)
    uint32_t ah[4][4], am[4][4];
    float    anr[2];
    {
        int r0 = strip + q, r1 = strip + q + 8;
        float a0 = 0.f, a1 = 0.f;
#pragma unroll
        for (int s = 0; s < 4; ++s) {
            int d0 = 16 * s + c2;
            float v0 = sA[(d0    ) * 260 + r0];
            float v1 = sA[(d0 + 1) * 260 + r0];
            float w0 = sA[(d0    ) * 260 + r1];
            float w1 = sA[(d0 + 1) * 260 + r1];
            float v2 = sA[(d0 + 8) * 260 + r0];
            float v3 = sA[(d0 + 9) * 260 + r0];
            float w2 = sA[(d0 + 8) * 260 + r1];
            float w3 = sA[(d0 + 9) * 260 + r1];
            a0 = fmaf(v0, v0, a0); a0 = fmaf(v1, v1, a0);
            a0 = fmaf(v2, v2, a0); a0 = fmaf(v3, v3, a0);
            a1 = fmaf(w0, w0, a1); a1 = fmaf(w1, w1, a1);
            a1 = fmaf(w2, w2, a1); a1 = fmaf(w3, w3, a1);
            float h0 = __bfloat162float(__float2bfloat16(v0));
            float h1 = __bfloat162float(__float2bfloat16(v1));
            float g0 = __bfloat162float(__float2bfloat16(w0));
            float g1 = __bfloat162float(__float2bfloat16(w1));
            float h2 = __bfloat162float(__float2bfloat16(v2));
            float h3 = __bfloat162float(__float2bfloat16(v3));
            float g2 = __bfloat162float(__float2bfloat16(w2));
            float g3 = __bfloat162float(__float2bfloat16(w3));
            ah[s][0] = packbf(h0, h1);
            ah[s][1] = packbf(g0, g1);
            ah[s][2] = packbf(h2, h3);
            ah[s][3] = packbf(g2, g3);
            am[s][0] = packbf(v0 - h0, v1 - h1);
            am[s][1] = packbf(w0 - g0, w1 - g1);
            am[s][2] = packbf(v2 - h2, v3 - h3);
            am[s][3] = packbf(w2 - g2, w3 - g3);
        }
        a0 += __shfl_xor_sync(0xffffffffu, a0, 1);
        a0 += __shfl_xor_sync(0xffffffffu, a0, 2);
        a1 += __shfl_xor_sync(0xffffffffu, a1, 1);
        a1 += __shfl_xor_sync(0xffffffffu, a1, 2);
        anr[0] = a0; anr[1] = a1;
    }
    __syncthreads();

    // --- phase 2: B tiles (eh | em), pre-swizzled, into smem ---
    {
        const uint4* src = (const uint4*)g_bsplit;
        uint4*       dst = (uint4*)smem;
        for (int i = tid; i < 8192; i += 512) dst[i] = src[i];
    }
    __syncthreads();

    // --- per-lane ldmatrix addressing ---
    const int sub = (lane >> 3) & 1;                    // k-half
    const int rc  = ((lane & 16) >> 1) + (lane & 7);    // code row within 16
    const int sw7 = lane & 7;
    uint32_t boff[4];
#pragma unroll
    for (int ks = 0; ks < 4; ++ks)
        boff[ks] = (uint32_t)(((2 * ks + sub) ^ sw7) << 4);

    const float* bn = (const float*)(smem + SM_BN);
    float d1[2] = {FLT_MAX, FLT_MAX};
    float d2[2] = {FLT_MAX, FLT_MAX};
    int   i1[2] = {0, 0};

#pragma unroll 1
    for (int j = 0; j < 32; ++j) {      // 32 groups of 16 codes
        uint32_t bj = sb + (uint32_t)(j * 16 + rc) * 128u;
        float c[4][2][4];               // 4 rotating accs x 2 n-tiles -> 8 chains
#pragma unroll
        for (int a = 0; a < 4; ++a)
#pragma unroll
            for (int nt = 0; nt < 2; ++nt)
#pragma unroll
                for (int r = 0; r < 4; ++r) c[a][nt][r] = 0.f;

#pragma unroll
        for (int ks = 0; ks < 4; ++ks) {
            uint32_t bh[4], bm[4];
            ldsm4(bh, bj + boff[ks]);             // eh fragment (reused twice)
            ldsm4(bm, bj + SM_EM + boff[ks]);     // em fragment
            int a0 = (3 * ks    ) & 3;
            int a1 = (3 * ks + 1) & 3;
            int a2 = (3 * ks + 2) & 3;
            mma16816(c[a0][0], ah[ks], bh[0], bh[1]);   // hh
            mma16816(c[a0][1], ah[ks], bh[2], bh[3]);
            mma16816(c[a1][0], ah[ks], bm[0], bm[1]);   // hm
            mma16816(c[a1][1], ah[ks], bm[2], bm[3]);
            mma16816(c[a2][0], am[ks], bh[0], bh[1]);   // mh
            mma16816(c[a2][1], am[ks], bh[2], bh[3]);
        }

        int cb = j * 16 + c2;
#pragma unroll
        for (int nt = 0; nt < 2; ++nt) {
            float s0 = (c[0][nt][0] + c[1][nt][0]) + (c[2][nt][0] + c[3][nt][0]);
            float s1 = (c[0][nt][1] + c[1][nt][1]) + (c[2][nt][1] + c[3][nt][1]);
            float s2 = (c[0][nt][2] + c[1][nt][2]) + (c[2][nt][2] + c[3][nt][2]);
            float s3 = (c[0][nt][3] + c[1][nt][3]) + (c[2][nt][3] + c[3][nt][3]);
            int k0 = cb + nt * 8, k1 = k0 + 1;
            float bn0 = bn[k0], bn1 = bn[k1];
            // C fragment: {c0,c1} = row q cols {k0,k1}; {c2,c3} = row q+8 cols {k0,k1}
            // replicate reference rounding: d = fl( fl(A + B) - 2*dot )
            float v0 = fmaf(s0, -2.f, anr[0] + bn0);   // row q,   code k0
            float v1 = fmaf(s1, -2.f, anr[0] + bn1);   // row q,   code k1
            float v2 = fmaf(s2, -2.f, anr[1] + bn0);   // row q+8, code k0
            float v3 = fmaf(s3, -2.f, anr[1] + bn1);   // row q+8, code k1
            if (v0 < d1[0]) { d2[0] = d1[0]; d1[0] = v0; i1[0] = k0; } else if (v0 < d2[0]) d2[0] = v0;
            if (v1 < d1[0]) { d2[0] = d1[0]; d1[0] = v1; i1[0] = k1; } else if (v1 < d2[0]) d2[0] = v1;
            if (v2 < d1[1]) { d2[1] = d1[1]; d1[1] = v2; i1[1] = k0; } else if (v2 < d2[1]) d2[1] = v2;
            if (v3 < d1[1]) { d2[1] = d1[1]; d1[1] = v3; i1[1] = k1; } else if (v3 < d2[1]) d2[1] = v3;
        }
    }

    // --- merge top-2 across quad lanes; flag near-ties; emit the rest ---
    float dloc = 0.f;
#pragma unroll
    for (int r = 0; r < 2; ++r) {
#pragma unroll
        for (int o = 1; o <= 2; o <<= 1) {
            float od1 = __shfl_xor_sync(0xffffffffu, d1[r], o);
            int   oi1 = __shfl_xor_sync(0xffffffffu, i1[r], o);
            float od2 = __shfl_xor_sync(0xffffffffu, d2[r], o);
            if (od1 < d1[r] || (od1 == d1[r] && oi1 < i1[r])) {
                d2[r] = fminf(d1[r], od2);
                d1[r] = od1; i1[r] = oi1;
            } else {
                d2[r] = fminf(d2[r], od1);
            }
        }
        if ((lane & 3) == 0) {
            int n = nbase + strip + q + r * 8;
            if (d2[r] - d1[r] < THETA) {
                int pos = atomicAdd(&g_nflag, 1);
                g_flag[pos] = n;
            } else {
                g_idx[n]         = i1[r];
                out[OFF_IDX + n] = (float)i1[r];
                atomicAdd(((uint32_t*)(smem + SM_HIST)) + i1[r], 1u);
                dloc += d1[r];
            }
        }
    }
#pragma unroll
    for (int o = 16; o; o >>= 1) dloc += __shfl_xor_sync(0xffffffffu, dloc, o);
    if (lane == 0) atomicAdd(&g_dsum, (double)dloc);

    __syncthreads();
    {
        uint32_t h = ((uint32_t*)(smem + SM_HIST))[tid];
        if (h) atomicAdd(&g_counts[tid], h);
    }
}

// ---- exact fp32 rescan of flagged (near-tie) tokens ----
__global__ void vq_fix(const float* __restrict__ z_e, const float* __restrict__ emb,
                       float* __restrict__ out) {
    int gw   = (blockIdx.x * 256 + threadIdx.x) >> 5;
    int lane = threadIdx.x & 31;
    int nf   = g_nflag;
    for (int i = gw; i < nf; i += 1024) {
        int n = g_flag[i];
        const float* zp = z_e + ((size_t)(n >> 12) << 18) + (n & (HW - 1));
        float z[64];
        float A = 0.f;
#pragma unroll
        for (int d = 0; d < 64; ++d) {
            z[d] = zp[(size_t)d << 12];
            A = fmaf(z[d], z[d], A);
        }
        float dmin = FLT_MAX;
        int   imin = 0;
        for (int c = lane; c < 512; c += 32) {
            const float* e = emb + c * 64;
            float t0 = 0.f, t1 = 0.f, t2 = 0.f, t3 = 0.f;
#pragma unroll
            for (int d = 0; d < 64; d += 4) {
                t0 = fmaf(z[d    ], e[d    ], t0);
                t1 = fmaf(z[d + 1], e[d + 1], t1);
                t2 = fmaf(z[d + 2], e[d + 2], t2);
                t3 = fmaf(z[d + 3], e[d + 3], t3);
            }
            float dot  = (t0 + t1) + (t2 + t3);
            float dist = fmaf(dot, -2.f, A + g_bnorm[c]);
            if (dist < dmin) { dmin = dist; imin = c; }
        }
#pragma unroll
        for (int o = 16; o; o >>= 1) {
            float od = __shfl_xor_sync(0xffffffffu, dmin, o);
            int   oi = __shfl_xor_sync(0xffffffffu, imin, o);
            if (od < dmin || (od == dmin && oi < imin)) { dmin = od; imin = oi; }
        }
        if (lane == 0) {
            g_idx[n]         = imin;
            out[OFF_IDX + n] = (float)imin;
            atomicAdd(&g_counts[imin], 1u);
            atomicAdd(&g_dsum, (double)dmin);
        }
    }
}

// ---- z_q scatter: out[b,d,h,w] = emb[idx[b,h,w], d] ----
__global__ void vq_zq(const float* __restrict__ emb, float* __restrict__ out) {
    int t  = blockIdx.x * 256 + threadIdx.x;
    int hw = t & (HW - 1);
    int d4 = (t >> 12) & 15;
    int b  = t >> 16;
    int idx = g_idx[(b << 12) + hw];
    const float4 e = *(const float4*)(emb + idx * 64 + d4 * 4);
    int base = (b << 18) + (d4 << 14) + hw;
    out[base        ] = e.x;
    out[base +  4096] = e.y;
    out[base +  8192] = e.z;
    out[base + 12288] = e.w;
}

// ---- scalars ----
__global__ void vq_finalize(float* __restrict__ out) {
    __shared__ float s_e[16];
    __shared__ int   s_u[16];
    int k = threadIdx.x;
    unsigned int c = g_counts[k];
    float p = (float)c * (1.0f / 131072.0f);
    float e = (c > 0) ? -p * logf(p) : 0.0f;
    int   u = (c > 0) ? 1 : 0;
#pragma unroll
    for (int o = 16; o; o >>= 1) {
        e += __shfl_xor_sync(0xffffffffu, e, o);
        u += __shfl_xor_sync(0xffffffffu, u, o);
    }
    if ((k & 31) == 0) { s_e[k >> 5] = e; s_u[k >> 5] = u; }
    __syncthreads();
    if (k == 0) {
        float ent = 0.0f; int used = 0;
        for (int i = 0; i < 16; ++i) { ent += s_e[i]; used += s_u[i]; }
        float avg = (float)(g_dsum * (1.0 / 131072.0));
        out[OFF_SCAL + 0] = 1.25f * avg;
        out[OFF_SCAL + 1] = expf(ent);
        out[OFF_SCAL + 2] = (float)used;
        out[OFF_SCAL + 3] = (float)used / 512.0f;
        out[OFF_SCAL + 4] = avg;
    }
}

extern "C" void kernel_launch(void* const* d_in, const int* in_sizes, int n_in,
                              void* d_out, int out_size) {
    const float* z_e = (const float*)d_in[0];
    const float* emb = (const float*)d_in[1];
    float*       out = (float*)d_out;

    cudaFuncSetAttribute(vq_screen, cudaFuncAttributeMaxDynamicSharedMemorySize,
                         SM_TOTAL);

    vq_prep<<<2, 256>>>(emb);
    vq_screen<<<N_TOK / 256, 512, SM_TOTAL>>>(z_e, out);
    vq_fix<<<128, 256>>>(z_e, emb, out);
    vq_zq<<<(N_TOK * 16) / 256, 256>>>(emb, out);
    vq_finalize<<<1, 512>>>(out);
}